// round 1
// baseline (speedup 1.0000x reference)
#include <cuda_runtime.h>

#define N_NODES 100000
#define N_EDGES 1600000
#define D_IN    512
#define D_OUT   64

#define SCAN_BLK 1024
#define N_SCAN_BLKS ((N_NODES + SCAN_BLK - 1) / SCAN_BLK)   // 98

// ---------------- scratch (device globals; no allocation allowed) -------------
__device__ float g_h[N_NODES * D_OUT];          // 25.6 MB, stays L2-resident
__device__ int   g_deg[N_NODES];
__device__ int   g_rowstart[N_NODES + 1];
__device__ int   g_cursor[N_NODES];
__device__ int   g_bsum[128];
__device__ int   g_boff[128];
__device__ int   g_csr_col[N_EDGES];
__device__ float g_csr_val[N_EDGES];

// ---------------- GEMM: h = X @ W  (fp32 SIMT, 64x64 tile, 4x4 microtile) ----
#define BM 64
#define BK 16

__global__ void k_gemm(const float* __restrict__ X, const float* __restrict__ W) {
    __shared__ __align__(16) float as[BK][BM + 4];     // X^T tile
    __shared__ __align__(16) float bs[BK][D_OUT + 4];  // W tile

    const int tid = threadIdx.x;            // 256 threads
    const int block_row = blockIdx.x * BM;

    const int tx = tid & 15;                // col group (4 cols)
    const int ty = tid >> 4;                // row group (4 rows)

    // global-load mapping
    const int lr = tid >> 2;                // 0..63 row within tile
    const int lk = (tid & 3) * 4;           // k offset (float4)
    const int wk = tid >> 4;                // 0..15 k row for W
    const int wc = (tid & 15) * 4;          // col offset for W

    float acc[4][4] = {};

    for (int k0 = 0; k0 < D_IN; k0 += BK) {
        const int grow = block_row + lr;
        float4 xa = make_float4(0.f, 0.f, 0.f, 0.f);
        if (grow < N_NODES)
            xa = *(const float4*)&X[(long)grow * D_IN + k0 + lk];
        as[lk + 0][lr] = xa.x;
        as[lk + 1][lr] = xa.y;
        as[lk + 2][lr] = xa.z;
        as[lk + 3][lr] = xa.w;

        *(float4*)&bs[wk][wc] = *(const float4*)&W[(k0 + wk) * D_OUT + wc];

        __syncthreads();

        #pragma unroll
        for (int kk = 0; kk < BK; kk++) {
            const float4 a = *(const float4*)&as[kk][ty * 4];
            const float4 b = *(const float4*)&bs[kk][tx * 4];
            acc[0][0] += a.x * b.x; acc[0][1] += a.x * b.y; acc[0][2] += a.x * b.z; acc[0][3] += a.x * b.w;
            acc[1][0] += a.y * b.x; acc[1][1] += a.y * b.y; acc[1][2] += a.y * b.z; acc[1][3] += a.y * b.w;
            acc[2][0] += a.z * b.x; acc[2][1] += a.z * b.y; acc[2][2] += a.z * b.z; acc[2][3] += a.z * b.w;
            acc[3][0] += a.w * b.x; acc[3][1] += a.w * b.y; acc[3][2] += a.w * b.z; acc[3][3] += a.w * b.w;
        }
        __syncthreads();
    }

    #pragma unroll
    for (int i = 0; i < 4; i++) {
        const int grow = block_row + ty * 4 + i;
        if (grow < N_NODES) {
            *(float4*)&g_h[(long)grow * D_OUT + tx * 4] =
                make_float4(acc[i][0], acc[i][1], acc[i][2], acc[i][3]);
        }
    }
}

// ---------------- CSR build ---------------------------------------------------
__global__ void k_zero_deg() {
    int i = blockIdx.x * blockDim.x + threadIdx.x;
    if (i < N_NODES) g_deg[i] = 0;
}

__global__ void k_count(const int* __restrict__ rows) {
    int e = blockIdx.x * blockDim.x + threadIdx.x;
    if (e < N_EDGES) atomicAdd(&g_deg[rows[e]], 1);
}

// block-level exclusive scan of deg -> partial rowstart, block totals -> g_bsum
__global__ void k_scan1() {
    __shared__ int wsum[32];
    const int i = blockIdx.x * SCAN_BLK + threadIdx.x;
    const int v = (i < N_NODES) ? g_deg[i] : 0;
    const int lane = threadIdx.x & 31;
    const int w = threadIdx.x >> 5;

    int x = v;
    #pragma unroll
    for (int o = 1; o < 32; o <<= 1) {
        int y = __shfl_up_sync(0xffffffffu, x, o);
        if (lane >= o) x += y;
    }
    if (lane == 31) wsum[w] = x;
    __syncthreads();
    if (w == 0) {
        int s = wsum[lane];
        int t = s;
        #pragma unroll
        for (int o = 1; o < 32; o <<= 1) {
            int y = __shfl_up_sync(0xffffffffu, t, o);
            if (lane >= o) t += y;
        }
        wsum[lane] = t - s;                       // exclusive warp offsets
        if (lane == 31) g_bsum[blockIdx.x] = t;   // block total
    }
    __syncthreads();
    const int excl = x - v + wsum[w];
    if (i < N_NODES) g_rowstart[i] = excl;
}

// exclusive scan over the 98 block totals (single block, 128 threads = 4 warps)
__global__ void k_scan2() {
    __shared__ int wsum[4];
    const int tid = threadIdx.x;
    const int lane = tid & 31;
    const int w = tid >> 5;
    const int v = (tid < N_SCAN_BLKS) ? g_bsum[tid] : 0;
    int x = v;
    #pragma unroll
    for (int o = 1; o < 32; o <<= 1) {
        int y = __shfl_up_sync(0xffffffffu, x, o);
        if (lane >= o) x += y;
    }
    if (lane == 31) wsum[w] = x;
    __syncthreads();
    int woff = 0;
    for (int j = 0; j < w; j++) woff += wsum[j];
    if (tid < N_SCAN_BLKS) g_boff[tid] = x - v + woff;
}

__global__ void k_scan3() {
    const int i = blockIdx.x * SCAN_BLK + threadIdx.x;
    if (i < N_NODES) {
        const int val = g_rowstart[i] + g_boff[blockIdx.x];
        g_rowstart[i] = val;
        g_cursor[i] = val;
    }
    if (i == 0) g_rowstart[N_NODES] = N_EDGES;
}

__global__ void k_fill(const float* __restrict__ vals,
                       const int* __restrict__ rows,
                       const int* __restrict__ cols) {
    int e = blockIdx.x * blockDim.x + threadIdx.x;
    if (e < N_EDGES) {
        const int r = rows[e];
        const int p = atomicAdd(&g_cursor[r], 1);
        g_csr_col[p] = cols[e];
        g_csr_val[p] = vals[e];
    }
}

// ---------------- SpMM + ReLU: warp per row, float2 per lane ------------------
__global__ void k_spmm(float* __restrict__ out) {
    const int gwarp = (blockIdx.x * blockDim.x + threadIdx.x) >> 5;
    const int lane = threadIdx.x & 31;
    if (gwarp >= N_NODES) return;

    const int s = g_rowstart[gwarp];
    const int e = g_rowstart[gwarp + 1];

    const float2* __restrict__ h2 = (const float2*)g_h;
    float2 acc = make_float2(0.f, 0.f);

    for (int j = s; j < e; j += 32) {
        const int jj = j + lane;
        int   c = 0;
        float v = 0.f;
        if (jj < e) {
            c = g_csr_col[jj];
            v = g_csr_val[jj];
        }
        const int cnt = min(32, e - j);
        for (int i = 0; i < cnt; i++) {
            const int   ci = __shfl_sync(0xffffffffu, c, i);
            const float vi = __shfl_sync(0xffffffffu, v, i);
            const float2 hv = h2[(long)ci * 32 + lane];
            acc.x = fmaf(vi, hv.x, acc.x);
            acc.y = fmaf(vi, hv.y, acc.y);
        }
    }

    acc.x = fmaxf(acc.x, 0.f);
    acc.y = fmaxf(acc.y, 0.f);
    ((float2*)out)[(long)gwarp * 32 + lane] = acc;
}

// ---------------- launch ------------------------------------------------------
extern "C" void kernel_launch(void* const* d_in, const int* in_sizes, int n_in,
                              void* d_out, int out_size) {
    const float* X    = (const float*)d_in[0];   // [N, 512]
    const float* W    = (const float*)d_in[1];   // [512, 64]
    const float* vals = (const float*)d_in[2];   // [E]
    const int*   rows = (const int*)d_in[3];     // [E]
    const int*   cols = (const int*)d_in[4];     // [E]
    float* out = (float*)d_out;                  // [N, 64]

    // GEMM: h = X @ W
    k_gemm<<<(N_NODES + BM - 1) / BM, 256>>>(X, W);

    // CSR build
    k_zero_deg<<<(N_NODES + 255) / 256, 256>>>();
    k_count<<<(N_EDGES + 255) / 256, 256>>>(rows);
    k_scan1<<<N_SCAN_BLKS, SCAN_BLK>>>();
    k_scan2<<<1, 128>>>();
    k_scan3<<<N_SCAN_BLKS, SCAN_BLK>>>();
    k_fill<<<(N_EDGES + 255) / 256, 256>>>(vals, rows, cols);

    // aggregate + relu  (warp per row: 8 warps/block)
    k_spmm<<<(N_NODES + 7) / 8, 256>>>(out);
}

// round 3
// speedup vs baseline: 1.4215x; 1.4215x over previous
#include <cuda_runtime.h>
#include <cstdint>

#define N_NODES 100000
#define N_EDGES 1600000
#define D_IN    512
#define D_OUT   64

#define SCAN_BLK 1024
#define N_SCAN_BLKS ((N_NODES + SCAN_BLK - 1) / SCAN_BLK)   // 98

#define TILES   782            // ceil(100000/128)
#define GGRID   152            // persistent CTAs (GB300: 152 SMs)

#define B_STRIDE 72            // floats per W row in smem (64 + 8 pad)
#define A_STRIDE 36            // floats per A row in smem (32 + 4 pad)
#define B_SMEM_FLOATS (D_IN * B_STRIDE)            // 36864
#define A_SMEM_FLOATS (128 * A_STRIDE)             // 4608 per buffer
#define SMEM_TOTAL ((B_SMEM_FLOATS + 2 * A_SMEM_FLOATS) * 4)   // 184320 B

// ---------------- scratch (device globals; no allocation allowed) -------------
__device__ float g_h[N_NODES * D_OUT];          // 25.6 MB
__device__ int   g_deg[N_NODES];
__device__ int   g_rowstart[N_NODES + 1];
__device__ int   g_cursor[N_NODES];
__device__ int   g_bsum[128];
__device__ int   g_boff[128];
__device__ int   g_csr_col[N_EDGES];
__device__ float g_csr_val[N_EDGES];

// ---------------- helpers -----------------------------------------------------
__device__ __forceinline__ uint32_t f2tf32(float f) {
    uint32_t r;
    asm("cvt.rna.tf32.f32 %0, %1;" : "=r"(r) : "f"(f));
    return r;
}

__device__ __forceinline__ void mma_tf32(float c[4],
                                         uint32_t a0, uint32_t a1, uint32_t a2, uint32_t a3,
                                         uint32_t b0, uint32_t b1) {
    asm volatile(
        "mma.sync.aligned.m16n8k8.row.col.f32.tf32.tf32.f32 "
        "{%0,%1,%2,%3}, {%4,%5,%6,%7}, {%8,%9}, {%0,%1,%2,%3};"
        : "+f"(c[0]), "+f"(c[1]), "+f"(c[2]), "+f"(c[3])
        : "r"(a0), "r"(a1), "r"(a2), "r"(a3), "r"(b0), "r"(b1));
}

// ---------------- GEMM: h = X @ W via mma.sync tf32 ---------------------------
__global__ __launch_bounds__(256, 1) void k_gemm_tc(const float* __restrict__ X,
                                                    const float* __restrict__ W) {
    extern __shared__ uint32_t smem[];
    uint32_t* const Bs = smem;                         // [512][72] tf32
    uint32_t* const As = smem + B_SMEM_FLOATS;         // 2 x [128][36] tf32

    const int tid  = threadIdx.x;
    const int bx   = blockIdx.x;
    const int warp = tid >> 5;
    const int lane = tid & 31;
    const int grp  = lane >> 2;       // 0..7
    const int tig  = lane & 3;        // 0..3
    const int moff = warp * 16;

    // ---- load whole W into smem as tf32, [k][n] with stride 72 ----
    for (int i = tid * 4; i < D_IN * D_OUT; i += 1024) {
        const int kk = i >> 6, nn = i & 63;
        float4 v = *(const float4*)&W[i];
        uint32_t* d = Bs + kk * B_STRIDE + nn;
        d[0] = f2tf32(v.x); d[1] = f2tf32(v.y); d[2] = f2tf32(v.z); d[3] = f2tf32(v.w);
    }

    const int my_tiles = (TILES - bx + GGRID - 1) / GGRID;
    const int nchunks  = my_tiles * 16;
    if (nchunks == 0) return;

    // per-thread A ldg/sts mapping: row = tid>>1 (0..127), col half = (tid&1)*16
    const int arow  = tid >> 1;
    const int acol  = (tid & 1) * 16;

    float4 pf[4];
    // prologue: chunk 0
    {
        const int tile = bx;
        const int grow = tile * 128 + arow;
        const float* p = X + (size_t)grow * D_IN + acol;
        const bool ok = grow < N_NODES;
        #pragma unroll
        for (int j = 0; j < 4; j++)
            pf[j] = ok ? *(const float4*)(p + 4 * j) : make_float4(0.f, 0.f, 0.f, 0.f);
        uint32_t* d = As + arow * A_STRIDE + acol;
        #pragma unroll
        for (int j = 0; j < 4; j++) {
            d[4*j+0] = f2tf32(pf[j].x); d[4*j+1] = f2tf32(pf[j].y);
            d[4*j+2] = f2tf32(pf[j].z); d[4*j+3] = f2tf32(pf[j].w);
        }
    }

    float acc[8][4];
    #pragma unroll
    for (int j = 0; j < 8; j++)
        #pragma unroll
        for (int e = 0; e < 4; e++) acc[j][e] = 0.f;

    for (int c = 0; c < nchunks; c++) {
        // prefetch chunk c+1 into regs
        if (c + 1 < nchunks) {
            const int tile = bx + ((c + 1) >> 4) * GGRID;
            const int grow = tile * 128 + arow;
            const int k0   = ((c + 1) & 15) * 32 + acol;
            const float* p = X + (size_t)grow * D_IN + k0;
            const bool ok = grow < N_NODES;
            #pragma unroll
            for (int j = 0; j < 4; j++)
                pf[j] = ok ? *(const float4*)(p + 4 * j) : make_float4(0.f, 0.f, 0.f, 0.f);
        }

        __syncthreads();   // A[c&1] visible to all; prev buffer free for overwrite

        // ---- compute chunk c ----
        const uint32_t* Ab = As + (size_t)(c & 1) * A_SMEM_FLOATS
                           + (moff + grp) * A_STRIDE + tig;
        const int kbase = (c & 15) * 32;
        #pragma unroll
        for (int ks = 0; ks < 4; ks++) {
            const uint32_t a0 = Ab[ks * 8];
            const uint32_t a1 = Ab[8 * A_STRIDE + ks * 8];
            const uint32_t a2 = Ab[ks * 8 + 4];
            const uint32_t a3 = Ab[8 * A_STRIDE + ks * 8 + 4];
            const uint32_t* Bb = Bs + (size_t)(kbase + ks * 8 + tig) * B_STRIDE + grp;
            #pragma unroll
            for (int j = 0; j < 8; j++) {
                const uint32_t b0 = Bb[j * 8];
                const uint32_t b1 = Bb[4 * B_STRIDE + j * 8];
                mma_tf32(acc[j], a0, a1, a2, a3, b0, b1);
            }
        }

        // ---- store A chunk c+1 ----
        if (c + 1 < nchunks) {
            uint32_t* d = As + (size_t)((c + 1) & 1) * A_SMEM_FLOATS
                        + arow * A_STRIDE + acol;
            #pragma unroll
            for (int j = 0; j < 4; j++) {
                d[4*j+0] = f2tf32(pf[j].x); d[4*j+1] = f2tf32(pf[j].y);
                d[4*j+2] = f2tf32(pf[j].z); d[4*j+3] = f2tf32(pf[j].w);
            }
        }

        // ---- tile epilogue ----
        if ((c & 15) == 15) {
            const int tile = bx + (c >> 4) * GGRID;
            const int r0 = tile * 128 + moff + grp;
            const int r1 = r0 + 8;
            #pragma unroll
            for (int j = 0; j < 8; j++) {
                const int col = j * 8 + tig * 2;
                if (r0 < N_NODES)
                    *(float2*)&g_h[(size_t)r0 * D_OUT + col] = make_float2(acc[j][0], acc[j][1]);
                if (r1 < N_NODES)
                    *(float2*)&g_h[(size_t)r1 * D_OUT + col] = make_float2(acc[j][2], acc[j][3]);
                acc[j][0] = acc[j][1] = acc[j][2] = acc[j][3] = 0.f;
            }
        }
    }
}

// ---------------- CSR build ---------------------------------------------------
__global__ void k_zero_deg() {
    int i = blockIdx.x * blockDim.x + threadIdx.x;
    if (i < N_NODES) g_deg[i] = 0;
}

__global__ void k_count(const int* __restrict__ rows) {
    int e = blockIdx.x * blockDim.x + threadIdx.x;
    if (e < N_EDGES) atomicAdd(&g_deg[rows[e]], 1);
}

__global__ void k_scan1() {
    __shared__ int wsum[32];
    const int i = blockIdx.x * SCAN_BLK + threadIdx.x;
    const int v = (i < N_NODES) ? g_deg[i] : 0;
    const int lane = threadIdx.x & 31;
    const int w = threadIdx.x >> 5;

    int x = v;
    #pragma unroll
    for (int o = 1; o < 32; o <<= 1) {
        int y = __shfl_up_sync(0xffffffffu, x, o);
        if (lane >= o) x += y;
    }
    if (lane == 31) wsum[w] = x;
    __syncthreads();
    if (w == 0) {
        int s = wsum[lane];
        int t = s;
        #pragma unroll
        for (int o = 1; o < 32; o <<= 1) {
            int y = __shfl_up_sync(0xffffffffu, t, o);
            if (lane >= o) t += y;
        }
        wsum[lane] = t - s;
        if (lane == 31) g_bsum[blockIdx.x] = t;
    }
    __syncthreads();
    const int excl = x - v + wsum[w];
    if (i < N_NODES) g_rowstart[i] = excl;
}

__global__ void k_scan2() {
    __shared__ int wsum[4];
    const int tid = threadIdx.x;
    const int lane = tid & 31;
    const int w = tid >> 5;
    const int v = (tid < N_SCAN_BLKS) ? g_bsum[tid] : 0;
    int x = v;
    #pragma unroll
    for (int o = 1; o < 32; o <<= 1) {
        int y = __shfl_up_sync(0xffffffffu, x, o);
        if (lane >= o) x += y;
    }
    if (lane == 31) wsum[w] = x;
    __syncthreads();
    int woff = 0;
    for (int j = 0; j < w; j++) woff += wsum[j];
    if (tid < N_SCAN_BLKS) g_boff[tid] = x - v + woff;
}

__global__ void k_scan3() {
    const int i = blockIdx.x * SCAN_BLK + threadIdx.x;
    if (i < N_NODES) {
        const int val = g_rowstart[i] + g_boff[blockIdx.x];
        g_rowstart[i] = val;
        g_cursor[i] = val;
    }
    if (i == 0) g_rowstart[N_NODES] = N_EDGES;
}

__global__ void k_fill(const float* __restrict__ vals,
                       const int* __restrict__ rows,
                       const int* __restrict__ cols) {
    int e = blockIdx.x * blockDim.x + threadIdx.x;
    if (e < N_EDGES) {
        const int r = rows[e];
        const int p = atomicAdd(&g_cursor[r], 1);
        g_csr_col[p] = cols[e];
        g_csr_val[p] = vals[e];
    }
}

// ---------------- SpMM + ReLU: warp per row -----------------------------------
__global__ void k_spmm(float* __restrict__ out) {
    const int gwarp = (blockIdx.x * blockDim.x + threadIdx.x) >> 5;
    const int lane = threadIdx.x & 31;
    if (gwarp >= N_NODES) return;

    const int s = g_rowstart[gwarp];
    const int e = g_rowstart[gwarp + 1];

    const float2* __restrict__ h2 = (const float2*)g_h;
    float2 acc = make_float2(0.f, 0.f);

    for (int j = s; j < e; j += 32) {
        const int jj = j + lane;
        int   c = 0;
        float v = 0.f;
        if (jj < e) {
            c = g_csr_col[jj];
            v = g_csr_val[jj];
        }
        const int cnt = min(32, e - j);
        for (int i = 0; i < cnt; i++) {
            const int   ci = __shfl_sync(0xffffffffu, c, i);
            const float vi = __shfl_sync(0xffffffffu, v, i);
            const float2 hv = h2[(size_t)ci * 32 + lane];
            acc.x = fmaf(vi, hv.x, acc.x);
            acc.y = fmaf(vi, hv.y, acc.y);
        }
    }

    acc.x = fmaxf(acc.x, 0.f);
    acc.y = fmaxf(acc.y, 0.f);
    ((float2*)out)[(size_t)gwarp * 32 + lane] = acc;
}

// ---------------- launch ------------------------------------------------------
extern "C" void kernel_launch(void* const* d_in, const int* in_sizes, int n_in,
                              void* d_out, int out_size) {
    const float* X    = (const float*)d_in[0];
    const float* W    = (const float*)d_in[1];
    const float* vals = (const float*)d_in[2];
    const int*   rows = (const int*)d_in[3];
    const int*   cols = (const int*)d_in[4];
    float* out = (float*)d_out;

    static bool attr_set = false;
    if (!attr_set) {
        cudaFuncSetAttribute(k_gemm_tc, cudaFuncAttributeMaxDynamicSharedMemorySize,
                             SMEM_TOTAL);
        attr_set = true;
    }

    k_gemm_tc<<<GGRID, 256, SMEM_TOTAL>>>(X, W);

    k_zero_deg<<<(N_NODES + 255) / 256, 256>>>();
    k_count<<<(N_EDGES + 255) / 256, 256>>>(rows);
    k_scan1<<<N_SCAN_BLKS, SCAN_BLK>>>();
    k_scan2<<<1, 128>>>();
    k_scan3<<<N_SCAN_BLKS, SCAN_BLK>>>();
    k_fill<<<(N_EDGES + 255) / 256, 256>>>(vals, rows, cols);

    k_spmm<<<(N_NODES + 7) / 8, 256>>>(out);
}

// round 4
// speedup vs baseline: 1.5256x; 1.0732x over previous
#include <cuda_runtime.h>
#include <cuda_fp16.h>
#include <cstdint>

#define N_NODES 100000
#define N_EDGES 1600000
#define D_IN    512
#define D_OUT   64

#define SCAN_BLK 1024
#define N_SCAN_BLKS ((N_NODES + SCAN_BLK - 1) / SCAN_BLK)   // 98

#define TILES   782            // ceil(100000/128)
#define GGRID   152            // persistent CTAs

#define BS 72                  // halves per W row in smem (64 + 8 pad); 9*16B -> conflict-free
#define AS 40                  // halves per A row in smem (32 + 8 pad); 5*16B -> conflict-free
#define B_SMEM_HALVES (D_IN * BS)          // 36864  (73728 B)
#define A_SMEM_HALVES (128 * AS)           // 5120 per buffer (10240 B)
#define SMEM_TOTAL ((B_SMEM_HALVES + 2 * A_SMEM_HALVES) * 2)  // 94208 B

// ---------------- scratch -----------------------------------------------------
__device__ float g_h[N_NODES * D_OUT];
__device__ int   g_deg[N_NODES];
__device__ int   g_rowstart[N_NODES + 1];
__device__ int   g_cursor[N_NODES];
__device__ int   g_bsum[128];
__device__ int   g_boff[128];
__device__ int   g_csr_col[N_EDGES];
__device__ float g_csr_val[N_EDGES];

// ---------------- helpers -----------------------------------------------------
__device__ __forceinline__ uint32_t smem_u32(const void* p) {
    uint32_t a;
    asm("{ .reg .u64 t; cvta.to.shared.u64 t, %1; cvt.u32.u64 %0, t; }"
        : "=r"(a) : "l"(p));
    return a;
}

__device__ __forceinline__ uint32_t pack_h2(float lo, float hi) {
    __half2 h = __floats2half2_rn(lo, hi);
    return *reinterpret_cast<uint32_t*>(&h);
}

__device__ __forceinline__ void ldsm_x4(uint32_t addr, uint32_t r[4]) {
    asm volatile("ldmatrix.sync.aligned.m8n8.x4.shared.b16 {%0,%1,%2,%3}, [%4];"
                 : "=r"(r[0]), "=r"(r[1]), "=r"(r[2]), "=r"(r[3]) : "r"(addr));
}

__device__ __forceinline__ void ldsm_x4_t(uint32_t addr, uint32_t r[4]) {
    asm volatile("ldmatrix.sync.aligned.m8n8.x4.trans.shared.b16 {%0,%1,%2,%3}, [%4];"
                 : "=r"(r[0]), "=r"(r[1]), "=r"(r[2]), "=r"(r[3]) : "r"(addr));
}

__device__ __forceinline__ void mma_f16(float c[4], const uint32_t a[4],
                                        uint32_t b0, uint32_t b1) {
    asm volatile(
        "mma.sync.aligned.m16n8k16.row.col.f32.f16.f16.f32 "
        "{%0,%1,%2,%3}, {%4,%5,%6,%7}, {%8,%9}, {%0,%1,%2,%3};"
        : "+f"(c[0]), "+f"(c[1]), "+f"(c[2]), "+f"(c[3])
        : "r"(a[0]), "r"(a[1]), "r"(a[2]), "r"(a[3]), "r"(b0), "r"(b1));
}

// ---------------- GEMM: h = X @ W via mma.sync fp16 ---------------------------
__global__ __launch_bounds__(256, 1) void k_gemm_tc(const float* __restrict__ X,
                                                    const float* __restrict__ W) {
    extern __shared__ __align__(16) __half hsm[];
    __half* const Bsm = hsm;                       // [512][72]
    __half* const Asm = hsm + B_SMEM_HALVES;       // 2 x [128][40]

    const int tid  = threadIdx.x;
    const int bx   = blockIdx.x;
    const int warp = tid >> 5;
    const int lane = tid & 31;
    const int grp  = lane >> 2;       // 0..7
    const int tig  = lane & 3;        // 0..3
    const int moff = warp * 16;

    const uint32_t b_base = smem_u32(Bsm);
    const uint32_t a_base = smem_u32(Asm);

    // ---- W -> smem fp16 [k][n] stride 72; each thread 4 floats -> uint2 ----
    for (int i = tid * 4; i < D_IN * D_OUT; i += 1024) {
        const int kk = i >> 6, nn = i & 63;
        float4 v = *(const float4*)&W[i];
        uint2 p;
        p.x = pack_h2(v.x, v.y);
        p.y = pack_h2(v.z, v.w);
        *(uint2*)(Bsm + kk * BS + nn) = p;
    }

    const int my_tiles = (TILES - bx + GGRID - 1) / GGRID;
    const int nchunks  = my_tiles * 16;
    if (nchunks == 0) return;

    const int arow = tid >> 1;            // 0..127
    const int acol = (tid & 1) * 16;      // half-row half

    float4 pf[4];
    {   // prologue: chunk 0 -> buffer 0
        const int grow = bx * 128 + arow;
        const float* p = X + (size_t)grow * D_IN + acol;
        const bool ok = grow < N_NODES;
        #pragma unroll
        for (int j = 0; j < 4; j++)
            pf[j] = ok ? *(const float4*)(p + 4 * j) : make_float4(0.f, 0.f, 0.f, 0.f);
        uint4 u0 = make_uint4(pack_h2(pf[0].x, pf[0].y), pack_h2(pf[0].z, pf[0].w),
                              pack_h2(pf[1].x, pf[1].y), pack_h2(pf[1].z, pf[1].w));
        uint4 u1 = make_uint4(pack_h2(pf[2].x, pf[2].y), pack_h2(pf[2].z, pf[2].w),
                              pack_h2(pf[3].x, pf[3].y), pack_h2(pf[3].z, pf[3].w));
        *(uint4*)(Asm + arow * AS + acol)     = u0;
        *(uint4*)(Asm + arow * AS + acol + 8) = u1;
    }

    float acc[8][4];
    #pragma unroll
    for (int j = 0; j < 8; j++)
        #pragma unroll
        for (int e = 0; e < 4; e++) acc[j][e] = 0.f;

    // ldmatrix lane address components
    const int l15 = lane & 15;
    const int lhi = (lane >> 4) << 3;

    for (int c = 0; c < nchunks; c++) {
        if (c + 1 < nchunks) {   // prefetch next chunk to regs
            const int tile = bx + ((c + 1) >> 4) * GGRID;
            const int grow = tile * 128 + arow;
            const int k0   = ((c + 1) & 15) * 32 + acol;
            const float* p = X + (size_t)grow * D_IN + k0;
            const bool ok = grow < N_NODES;
            #pragma unroll
            for (int j = 0; j < 4; j++)
                pf[j] = ok ? *(const float4*)(p + 4 * j) : make_float4(0.f, 0.f, 0.f, 0.f);
        }

        __syncthreads();

        // ---- compute chunk c ----
        const uint32_t abuf = a_base + (uint32_t)(c & 1) * (A_SMEM_HALVES * 2);
        const int kbase = (c & 15) * 32;
        #pragma unroll
        for (int ks = 0; ks < 2; ks++) {
            uint32_t a[4];
            ldsm_x4(abuf + 2 * ((moff + l15) * AS + ks * 16 + lhi), a);

            uint32_t b[8][2];
            const int kb = kbase + ks * 16;
            #pragma unroll
            for (int jj = 0; jj < 4; jj++) {
                uint32_t br[4];
                ldsm_x4_t(b_base + 2 * ((kb + l15) * BS + jj * 16 + lhi), br);
                b[2*jj][0]   = br[0];  b[2*jj][1]   = br[1];
                b[2*jj+1][0] = br[2];  b[2*jj+1][1] = br[3];
            }
            #pragma unroll
            for (int j = 0; j < 8; j++)
                mma_f16(acc[j], a, b[j][0], b[j][1]);
        }

        if (c + 1 < nchunks) {   // store next chunk
            __half* d = Asm + (size_t)((c + 1) & 1) * A_SMEM_HALVES + arow * AS + acol;
            uint4 u0 = make_uint4(pack_h2(pf[0].x, pf[0].y), pack_h2(pf[0].z, pf[0].w),
                                  pack_h2(pf[1].x, pf[1].y), pack_h2(pf[1].z, pf[1].w));
            uint4 u1 = make_uint4(pack_h2(pf[2].x, pf[2].y), pack_h2(pf[2].z, pf[2].w),
                                  pack_h2(pf[3].x, pf[3].y), pack_h2(pf[3].z, pf[3].w));
            *(uint4*)d       = u0;
            *(uint4*)(d + 8) = u1;
        }

        if ((c & 15) == 15) {    // tile epilogue
            const int tile = bx + (c >> 4) * GGRID;
            const int r0 = tile * 128 + moff + grp;
            const int r1 = r0 + 8;
            #pragma unroll
            for (int j = 0; j < 8; j++) {
                const int col = j * 8 + tig * 2;
                if (r0 < N_NODES)
                    *(float2*)&g_h[(size_t)r0 * D_OUT + col] = make_float2(acc[j][0], acc[j][1]);
                if (r1 < N_NODES)
                    *(float2*)&g_h[(size_t)r1 * D_OUT + col] = make_float2(acc[j][2], acc[j][3]);
                acc[j][0] = acc[j][1] = acc[j][2] = acc[j][3] = 0.f;
            }
        }
    }
}

// ---------------- CSR build ---------------------------------------------------
__global__ void k_zero_deg() {
    int i = blockIdx.x * blockDim.x + threadIdx.x;
    if (i < N_NODES) g_deg[i] = 0;
}

__global__ void k_count(const int* __restrict__ rows) {
    int e = blockIdx.x * blockDim.x + threadIdx.x;
    if (e < N_EDGES) atomicAdd(&g_deg[rows[e]], 1);
}

__global__ void k_scan1() {
    __shared__ int wsum[32];
    const int i = blockIdx.x * SCAN_BLK + threadIdx.x;
    const int v = (i < N_NODES) ? g_deg[i] : 0;
    const int lane = threadIdx.x & 31;
    const int w = threadIdx.x >> 5;

    int x = v;
    #pragma unroll
    for (int o = 1; o < 32; o <<= 1) {
        int y = __shfl_up_sync(0xffffffffu, x, o);
        if (lane >= o) x += y;
    }
    if (lane == 31) wsum[w] = x;
    __syncthreads();
    if (w == 0) {
        int s = wsum[lane];
        int t = s;
        #pragma unroll
        for (int o = 1; o < 32; o <<= 1) {
            int y = __shfl_up_sync(0xffffffffu, t, o);
            if (lane >= o) t += y;
        }
        wsum[lane] = t - s;
        if (lane == 31) g_bsum[blockIdx.x] = t;
    }
    __syncthreads();
    const int excl = x - v + wsum[w];
    if (i < N_NODES) g_rowstart[i] = excl;
}

__global__ void k_scan2() {
    __shared__ int wsum[4];
    const int tid = threadIdx.x;
    const int lane = tid & 31;
    const int w = tid >> 5;
    const int v = (tid < N_SCAN_BLKS) ? g_bsum[tid] : 0;
    int x = v;
    #pragma unroll
    for (int o = 1; o < 32; o <<= 1) {
        int y = __shfl_up_sync(0xffffffffu, x, o);
        if (lane >= o) x += y;
    }
    if (lane == 31) wsum[w] = x;
    __syncthreads();
    int woff = 0;
    for (int j = 0; j < w; j++) woff += wsum[j];
    if (tid < N_SCAN_BLKS) g_boff[tid] = x - v + woff;
}

__global__ void k_scan3() {
    const int i = blockIdx.x * SCAN_BLK + threadIdx.x;
    if (i < N_NODES) {
        const int val = g_rowstart[i] + g_boff[blockIdx.x];
        g_rowstart[i] = val;
        g_cursor[i] = val;
    }
    if (i == 0) g_rowstart[N_NODES] = N_EDGES;
}

__global__ void k_fill(const float* __restrict__ vals,
                       const int* __restrict__ rows,
                       const int* __restrict__ cols) {
    int e = blockIdx.x * blockDim.x + threadIdx.x;
    if (e < N_EDGES) {
        const int r = rows[e];
        const int p = atomicAdd(&g_cursor[r], 1);
        g_csr_col[p] = cols[e];
        g_csr_val[p] = vals[e];
    }
}

// ---------------- SpMM + ReLU: warp per row, 4-way MLP ------------------------
__global__ void k_spmm(float* __restrict__ out) {
    const int gwarp = (blockIdx.x * blockDim.x + threadIdx.x) >> 5;
    const int lane = threadIdx.x & 31;
    if (gwarp >= N_NODES) return;

    const int s = g_rowstart[gwarp];
    const int e = g_rowstart[gwarp + 1];

    const float2* __restrict__ h2 = (const float2*)g_h;
    float2 acc = make_float2(0.f, 0.f);

    for (int j = s; j < e; j += 32) {
        const int jj = j + lane;
        int   c = 0;
        float v = 0.f;
        if (jj < e) {
            c = g_csr_col[jj];
            v = g_csr_val[jj];
        }
        const int cnt = min(32, e - j);
        int i = 0;
        for (; i + 4 <= cnt; i += 4) {
            const int   c0 = __shfl_sync(0xffffffffu, c, i);
            const float v0 = __shfl_sync(0xffffffffu, v, i);
            const int   c1 = __shfl_sync(0xffffffffu, c, i + 1);
            const float v1 = __shfl_sync(0xffffffffu, v, i + 1);
            const int   c2 = __shfl_sync(0xffffffffu, c, i + 2);
            const float v2 = __shfl_sync(0xffffffffu, v, i + 2);
            const int   c3 = __shfl_sync(0xffffffffu, c, i + 3);
            const float v3 = __shfl_sync(0xffffffffu, v, i + 3);
            const float2 h0 = h2[(size_t)c0 * 32 + lane];
            const float2 h1 = h2[(size_t)c1 * 32 + lane];
            const float2 h3v = h2[(size_t)c3 * 32 + lane];
            const float2 h2v = h2[(size_t)c2 * 32 + lane];
            acc.x = fmaf(v0, h0.x, acc.x);  acc.y = fmaf(v0, h0.y, acc.y);
            acc.x = fmaf(v1, h1.x, acc.x);  acc.y = fmaf(v1, h1.y, acc.y);
            acc.x = fmaf(v2, h2v.x, acc.x); acc.y = fmaf(v2, h2v.y, acc.y);
            acc.x = fmaf(v3, h3v.x, acc.x); acc.y = fmaf(v3, h3v.y, acc.y);
        }
        for (; i < cnt; i++) {
            const int   ci = __shfl_sync(0xffffffffu, c, i);
            const float vi = __shfl_sync(0xffffffffu, v, i);
            const float2 hv = h2[(size_t)ci * 32 + lane];
            acc.x = fmaf(vi, hv.x, acc.x);
            acc.y = fmaf(vi, hv.y, acc.y);
        }
    }

    acc.x = fmaxf(acc.x, 0.f);
    acc.y = fmaxf(acc.y, 0.f);
    ((float2*)out)[(size_t)gwarp * 32 + lane] = acc;
}

// ---------------- launch ------------------------------------------------------
extern "C" void kernel_launch(void* const* d_in, const int* in_sizes, int n_in,
                              void* d_out, int out_size) {
    const float* X    = (const float*)d_in[0];
    const float* W    = (const float*)d_in[1];
    const float* vals = (const float*)d_in[2];
    const int*   rows = (const int*)d_in[3];
    const int*   cols = (const int*)d_in[4];
    float* out = (float*)d_out;

    static bool attr_set = false;
    if (!attr_set) {
        cudaFuncSetAttribute(k_gemm_tc, cudaFuncAttributeMaxDynamicSharedMemorySize,
                             SMEM_TOTAL);
        attr_set = true;
    }

    // gemm placed at launch index 3 so the ncu capture slot lands on it
    k_zero_deg<<<(N_NODES + 255) / 256, 256>>>();
    k_count<<<(N_EDGES + 255) / 256, 256>>>(rows);
    k_scan1<<<N_SCAN_BLKS, SCAN_BLK>>>();
    k_gemm_tc<<<GGRID, 256, SMEM_TOTAL>>>(X, W);
    k_scan2<<<1, 128>>>();
    k_scan3<<<N_SCAN_BLKS, SCAN_BLK>>>();
    k_fill<<<(N_EDGES + 255) / 256, 256>>>(vals, rows, cols);

    k_spmm<<<(N_NODES + 7) / 8, 256>>>(out);
}

// round 5
// speedup vs baseline: 1.7600x; 1.1537x over previous
#include <cuda_runtime.h>
#include <cuda_fp16.h>
#include <cstdint>

#define N_NODES 100000
#define N_EDGES 1600000
#define D_IN    512
#define D_OUT   64

#define SCAN_BLK 1024
#define N_SCAN_BLKS ((N_NODES + SCAN_BLK - 1) / SCAN_BLK)   // 98

#define TILE_M  256
#define TILES   391            // ceil(100000/256)
#define GGRID   152            // persistent CTAs
#define NTHREADS 512

#define BS 72                  // halves per W row in smem (64 + 8 pad)
#define AS 40                  // halves per A row in smem (32 + 8 pad)
#define B_SMEM_HALVES (D_IN * BS)            // 36864  (73728 B)
#define A_SMEM_HALVES (TILE_M * AS)          // 10240 per buffer (20480 B)
#define SMEM_TOTAL ((B_SMEM_HALVES + 2 * A_SMEM_HALVES) * 2)  // 114688 B

// ---------------- scratch -----------------------------------------------------
__device__ __half g_h[N_NODES * D_OUT];      // 12.8 MB, fp16
__device__ int   g_deg[N_NODES];
__device__ int   g_rowstart[N_NODES + 1];
__device__ int   g_cursor[N_NODES];
__device__ int   g_bsum[128];
__device__ int   g_boff[128];
__device__ int   g_csr_col[N_EDGES];
__device__ float g_csr_val[N_EDGES];

// ---------------- helpers -----------------------------------------------------
__device__ __forceinline__ uint32_t smem_u32(const void* p) {
    uint32_t a;
    asm("{ .reg .u64 t; cvta.to.shared.u64 t, %1; cvt.u32.u64 %0, t; }"
        : "=r"(a) : "l"(p));
    return a;
}

__device__ __forceinline__ uint32_t pack_h2(float lo, float hi) {
    __half2 h = __floats2half2_rn(lo, hi);
    return *reinterpret_cast<uint32_t*>(&h);
}

__device__ __forceinline__ void ldsm_x4(uint32_t addr, uint32_t r[4]) {
    asm volatile("ldmatrix.sync.aligned.m8n8.x4.shared.b16 {%0,%1,%2,%3}, [%4];"
                 : "=r"(r[0]), "=r"(r[1]), "=r"(r[2]), "=r"(r[3]) : "r"(addr));
}

__device__ __forceinline__ void ldsm_x4_t(uint32_t addr, uint32_t r[4]) {
    asm volatile("ldmatrix.sync.aligned.m8n8.x4.trans.shared.b16 {%0,%1,%2,%3}, [%4];"
                 : "=r"(r[0]), "=r"(r[1]), "=r"(r[2]), "=r"(r[3]) : "r"(addr));
}

__device__ __forceinline__ void mma_f16(float c[4], const uint32_t a[4],
                                        uint32_t b0, uint32_t b1) {
    asm volatile(
        "mma.sync.aligned.m16n8k16.row.col.f32.f16.f16.f32 "
        "{%0,%1,%2,%3}, {%4,%5,%6,%7}, {%8,%9}, {%0,%1,%2,%3};"
        : "+f"(c[0]), "+f"(c[1]), "+f"(c[2]), "+f"(c[3])
        : "r"(a[0]), "r"(a[1]), "r"(a[2]), "r"(a[3]), "r"(b0), "r"(b1));
}

// ---------------- GEMM: h = X @ W via mma.sync fp16, 512 thr, 256-row tiles ---
__global__ __launch_bounds__(NTHREADS, 1) void k_gemm_tc(const float* __restrict__ X,
                                                         const float* __restrict__ W) {
    extern __shared__ __align__(16) __half hsm[];
    __half* const Bsm = hsm;                       // [512][72]
    __half* const Asm = hsm + B_SMEM_HALVES;       // 2 x [256][40]

    const int tid  = threadIdx.x;
    const int bx   = blockIdx.x;
    const int warp = tid >> 5;        // 0..15
    const int lane = tid & 31;
    const int grp  = lane >> 2;       // 0..7
    const int tig  = lane & 3;        // 0..3
    const int moff = warp * 16;       // 0..240

    const uint32_t b_base = smem_u32(Bsm);
    const uint32_t a_base = smem_u32(Asm);

    // ---- W -> smem fp16 [k][n] stride 72 ----
    for (int i = tid * 4; i < D_IN * D_OUT; i += NTHREADS * 4) {
        const int kk = i >> 6, nn = i & 63;
        float4 v = *(const float4*)&W[i];
        uint2 p;
        p.x = pack_h2(v.x, v.y);
        p.y = pack_h2(v.z, v.w);
        *(uint2*)(Bsm + kk * BS + nn) = p;
    }

    const int my_tiles = (TILES - bx + GGRID - 1) / GGRID;
    const int nchunks  = my_tiles * 16;
    if (nchunks == 0) return;

    const int arow = tid >> 1;            // 0..255
    const int acol = (tid & 1) * 16;

    float4 pf[4];
    {   // prologue: chunk 0 -> buffer 0
        const int grow = bx * TILE_M + arow;
        const float* p = X + (size_t)grow * D_IN + acol;
        const bool ok = grow < N_NODES;
        #pragma unroll
        for (int j = 0; j < 4; j++)
            pf[j] = ok ? *(const float4*)(p + 4 * j) : make_float4(0.f, 0.f, 0.f, 0.f);
        uint4 u0 = make_uint4(pack_h2(pf[0].x, pf[0].y), pack_h2(pf[0].z, pf[0].w),
                              pack_h2(pf[1].x, pf[1].y), pack_h2(pf[1].z, pf[1].w));
        uint4 u1 = make_uint4(pack_h2(pf[2].x, pf[2].y), pack_h2(pf[2].z, pf[2].w),
                              pack_h2(pf[3].x, pf[3].y), pack_h2(pf[3].z, pf[3].w));
        *(uint4*)(Asm + arow * AS + acol)     = u0;
        *(uint4*)(Asm + arow * AS + acol + 8) = u1;
    }

    float acc[8][4];
    #pragma unroll
    for (int j = 0; j < 8; j++)
        #pragma unroll
        for (int e = 0; e < 4; e++) acc[j][e] = 0.f;

    const int l15 = lane & 15;
    const int lhi = (lane >> 4) << 3;

    for (int c = 0; c < nchunks; c++) {
        if (c + 1 < nchunks) {   // prefetch next chunk into regs
            const int tile = bx + ((c + 1) >> 4) * GGRID;
            const int grow = tile * TILE_M + arow;
            const int k0   = ((c + 1) & 15) * 32 + acol;
            const float* p = X + (size_t)grow * D_IN + k0;
            const bool ok = grow < N_NODES;
            #pragma unroll
            for (int j = 0; j < 4; j++)
                pf[j] = ok ? *(const float4*)(p + 4 * j) : make_float4(0.f, 0.f, 0.f, 0.f);
        }

        __syncthreads();

        // ---- compute chunk c ----
        const uint32_t abuf = a_base + (uint32_t)(c & 1) * (A_SMEM_HALVES * 2);
        const int kbase = (c & 15) * 32;
        #pragma unroll
        for (int ks = 0; ks < 2; ks++) {
            uint32_t a[4];
            ldsm_x4(abuf + 2 * ((moff + l15) * AS + ks * 16 + lhi), a);

            uint32_t b[8][2];
            const int kb = kbase + ks * 16;
            #pragma unroll
            for (int jj = 0; jj < 4; jj++) {
                uint32_t br[4];
                ldsm_x4_t(b_base + 2 * ((kb + l15) * BS + jj * 16 + lhi), br);
                b[2*jj][0]   = br[0];  b[2*jj][1]   = br[1];
                b[2*jj+1][0] = br[2];  b[2*jj+1][1] = br[3];
            }
            #pragma unroll
            for (int j = 0; j < 8; j++)
                mma_f16(acc[j], a, b[j][0], b[j][1]);
        }

        if (c + 1 < nchunks) {   // store next chunk to the other buffer
            __half* d = Asm + (size_t)((c + 1) & 1) * A_SMEM_HALVES + arow * AS + acol;
            uint4 u0 = make_uint4(pack_h2(pf[0].x, pf[0].y), pack_h2(pf[0].z, pf[0].w),
                                  pack_h2(pf[1].x, pf[1].y), pack_h2(pf[1].z, pf[1].w));
            uint4 u1 = make_uint4(pack_h2(pf[2].x, pf[2].y), pack_h2(pf[2].z, pf[2].w),
                                  pack_h2(pf[3].x, pf[3].y), pack_h2(pf[3].z, pf[3].w));
            *(uint4*)d       = u0;
            *(uint4*)(d + 8) = u1;
        }

        if ((c & 15) == 15) {    // tile epilogue -> g_h (fp16)
            const int tile = bx + (c >> 4) * GGRID;
            const int r0 = tile * TILE_M + moff + grp;
            const int r1 = r0 + 8;
            #pragma unroll
            for (int j = 0; j < 8; j++) {
                const int col = j * 8 + tig * 2;
                if (r0 < N_NODES)
                    *(uint32_t*)&g_h[(size_t)r0 * D_OUT + col] = pack_h2(acc[j][0], acc[j][1]);
                if (r1 < N_NODES)
                    *(uint32_t*)&g_h[(size_t)r1 * D_OUT + col] = pack_h2(acc[j][2], acc[j][3]);
                acc[j][0] = acc[j][1] = acc[j][2] = acc[j][3] = 0.f;
            }
        }
    }
}

// ---------------- CSR build ---------------------------------------------------
__global__ void k_zero_deg() {
    int i = blockIdx.x * blockDim.x + threadIdx.x;
    if (i < N_NODES) g_deg[i] = 0;
}

__global__ void k_count(const int* __restrict__ rows) {
    int e = blockIdx.x * blockDim.x + threadIdx.x;
    if (e < N_EDGES) atomicAdd(&g_deg[rows[e]], 1);
}

__global__ void k_scan1() {
    __shared__ int wsum[32];
    const int i = blockIdx.x * SCAN_BLK + threadIdx.x;
    const int v = (i < N_NODES) ? g_deg[i] : 0;
    const int lane = threadIdx.x & 31;
    const int w = threadIdx.x >> 5;

    int x = v;
    #pragma unroll
    for (int o = 1; o < 32; o <<= 1) {
        int y = __shfl_up_sync(0xffffffffu, x, o);
        if (lane >= o) x += y;
    }
    if (lane == 31) wsum[w] = x;
    __syncthreads();
    if (w == 0) {
        int s = wsum[lane];
        int t = s;
        #pragma unroll
        for (int o = 1; o < 32; o <<= 1) {
            int y = __shfl_up_sync(0xffffffffu, t, o);
            if (lane >= o) t += y;
        }
        wsum[lane] = t - s;
        if (lane == 31) g_bsum[blockIdx.x] = t;
    }
    __syncthreads();
    const int excl = x - v + wsum[w];
    if (i < N_NODES) g_rowstart[i] = excl;
}

__global__ void k_scan2() {
    __shared__ int wsum[4];
    const int tid = threadIdx.x;
    const int lane = tid & 31;
    const int w = tid >> 5;
    const int v = (tid < N_SCAN_BLKS) ? g_bsum[tid] : 0;
    int x = v;
    #pragma unroll
    for (int o = 1; o < 32; o <<= 1) {
        int y = __shfl_up_sync(0xffffffffu, x, o);
        if (lane >= o) x += y;
    }
    if (lane == 31) wsum[w] = x;
    __syncthreads();
    int woff = 0;
    for (int j = 0; j < w; j++) woff += wsum[j];
    if (tid < N_SCAN_BLKS) g_boff[tid] = x - v + woff;
}

__global__ void k_scan3() {
    const int i = blockIdx.x * SCAN_BLK + threadIdx.x;
    if (i < N_NODES) {
        const int val = g_rowstart[i] + g_boff[blockIdx.x];
        g_rowstart[i] = val;
        g_cursor[i] = val;
    }
    if (i == 0) g_rowstart[N_NODES] = N_EDGES;
}

__global__ void k_fill(const float* __restrict__ vals,
                       const int* __restrict__ rows,
                       const int* __restrict__ cols) {
    int e = blockIdx.x * blockDim.x + threadIdx.x;
    if (e < N_EDGES) {
        const int r = rows[e];
        const int p = atomicAdd(&g_cursor[r], 1);
        g_csr_col[p] = cols[e];
        g_csr_val[p] = vals[e];
    }
}

// ---------------- SpMM + ReLU: warp per row, fp16 h gather --------------------
__global__ void k_spmm(float* __restrict__ out) {
    const int gwarp = (blockIdx.x * blockDim.x + threadIdx.x) >> 5;
    const int lane = threadIdx.x & 31;
    if (gwarp >= N_NODES) return;

    const int s = g_rowstart[gwarp];
    const int e = g_rowstart[gwarp + 1];

    const __half2* __restrict__ h2 = (const __half2*)g_h;
    float2 acc = make_float2(0.f, 0.f);

    for (int j = s; j < e; j += 32) {
        const int jj = j + lane;
        int   c = 0;
        float v = 0.f;
        if (jj < e) {
            c = g_csr_col[jj];
            v = g_csr_val[jj];
        }
        const int cnt = min(32, e - j);
        int i = 0;
        for (; i + 4 <= cnt; i += 4) {
            const int   c0 = __shfl_sync(0xffffffffu, c, i);
            const float v0 = __shfl_sync(0xffffffffu, v, i);
            const int   c1 = __shfl_sync(0xffffffffu, c, i + 1);
            const float v1 = __shfl_sync(0xffffffffu, v, i + 1);
            const int   c2 = __shfl_sync(0xffffffffu, c, i + 2);
            const float v2 = __shfl_sync(0xffffffffu, v, i + 2);
            const int   c3 = __shfl_sync(0xffffffffu, c, i + 3);
            const float v3 = __shfl_sync(0xffffffffu, v, i + 3);
            const float2 h0 = __half22float2(h2[(size_t)c0 * 32 + lane]);
            const float2 h1 = __half22float2(h2[(size_t)c1 * 32 + lane]);
            const float2 hb = __half22float2(h2[(size_t)c2 * 32 + lane]);
            const float2 hc = __half22float2(h2[(size_t)c3 * 32 + lane]);
            acc.x = fmaf(v0, h0.x, acc.x); acc.y = fmaf(v0, h0.y, acc.y);
            acc.x = fmaf(v1, h1.x, acc.x); acc.y = fmaf(v1, h1.y, acc.y);
            acc.x = fmaf(v2, hb.x, acc.x); acc.y = fmaf(v2, hb.y, acc.y);
            acc.x = fmaf(v3, hc.x, acc.x); acc.y = fmaf(v3, hc.y, acc.y);
        }
        for (; i < cnt; i++) {
            const int   ci = __shfl_sync(0xffffffffu, c, i);
            const float vi = __shfl_sync(0xffffffffu, v, i);
            const float2 hv = __half22float2(h2[(size_t)ci * 32 + lane]);
            acc.x = fmaf(vi, hv.x, acc.x);
            acc.y = fmaf(vi, hv.y, acc.y);
        }
    }

    acc.x = fmaxf(acc.x, 0.f);
    acc.y = fmaxf(acc.y, 0.f);
    ((float2*)out)[(size_t)gwarp * 32 + lane] = acc;
}

// ---------------- launch ------------------------------------------------------
extern "C" void kernel_launch(void* const* d_in, const int* in_sizes, int n_in,
                              void* d_out, int out_size) {
    const float* X    = (const float*)d_in[0];
    const float* W    = (const float*)d_in[1];
    const float* vals = (const float*)d_in[2];
    const int*   rows = (const int*)d_in[3];
    const int*   cols = (const int*)d_in[4];
    float* out = (float*)d_out;

    static bool attr_set = false;
    if (!attr_set) {
        cudaFuncSetAttribute(k_gemm_tc, cudaFuncAttributeMaxDynamicSharedMemorySize,
                             SMEM_TOTAL);
        attr_set = true;
    }

    // gemm at launch index 3 so the ncu capture slot lands on it
    k_zero_deg<<<(N_NODES + 255) / 256, 256>>>();
    k_count<<<(N_EDGES + 255) / 256, 256>>>(rows);
    k_scan1<<<N_SCAN_BLKS, SCAN_BLK>>>();
    k_gemm_tc<<<GGRID, NTHREADS, SMEM_TOTAL>>>(X, W);
    k_scan2<<<1, 128>>>();
    k_scan3<<<N_SCAN_BLKS, SCAN_BLK>>>();
    k_fill<<<(N_EDGES + 255) / 256, 256>>>(vals, rows, cols);

    k_spmm<<<(N_NODES + 7) / 8, 256>>>(out);
}